// round 17
// baseline (speedup 1.0000x reference)
#include <cuda_runtime.h>

#define SEQ   512
#define BATCH 256
#define INDIM 15
#define HID   512
#define NB    128
#define TPB   512

typedef unsigned long long u64;

// ---- persistent device state ----
__device__ float g_xT[SEQ * 16 * BATCH];     // [t][kp(8)][b][par], k=15 zero-padded to 16
__device__ float g_h1[2][HID * BATCH];       // pair layout: [kp][b][par]
__device__ float g_h2[2][HID * BATCH];
__device__ float g_fc1[64 * BATCH];
__device__ unsigned g_arrive;
__device__ unsigned g_release;

__global__ void sync_init_kernel() { g_arrive = 0u; g_release = 0u; }

// ---- f32x2 helpers ----
__device__ __forceinline__ u64 pk2(float a, float b) {
    u64 r; asm("mov.b64 %0, {%1,%2};" : "=l"(r) : "f"(a), "f"(b)); return r;
}
__device__ __forceinline__ void upk2(u64 v, float& a, float& b) {
    asm("mov.b64 {%0,%1}, %2;" : "=f"(a), "=f"(b) : "l"(v));
}
__device__ __forceinline__ u64 ffma2(u64 a, u64 b, u64 c) {
    u64 d; asm("fma.rn.f32x2 %0, %1, %2, %3;" : "=l"(d) : "l"(a), "l"(b), "l"(c)); return d;
}

// ---- cp.async staging ----
__device__ __forceinline__ void cp16(unsigned saddr, const void* g) {
    asm volatile("cp.async.cg.shared.global [%0], [%1], 16;" :: "r"(saddr), "l"(g));
}
__device__ __forceinline__ void cp_commit() { asm volatile("cp.async.commit_group;" ::: "memory"); }
__device__ __forceinline__ void cp_wait0()  { asm volatile("cp.async.wait_group 0;"  ::: "memory"); }

__device__ __forceinline__ void stage(float* dst, const float* src, int nf4, int tid) {
    unsigned s = (unsigned)__cvta_generic_to_shared(dst);
    const float4* g = (const float4*)src;
#pragma unroll 4
    for (int q = tid; q < nf4; q += TPB) cp16(s + q * 16, (const void*)(g + q));
}

// ---- grid-wide barrier ----
__device__ __forceinline__ void grid_sync(unsigned k) {
    __threadfence();
    __syncthreads();
    if (threadIdx.x == 0) {
        if (atomicAdd(&g_arrive, 1u) == k * (unsigned)NB - 1u) {
            asm volatile("st.release.gpu.global.u32 [%0], %1;" :: "l"(&g_release), "r"(k) : "memory");
        } else {
            unsigned v;
            do { asm volatile("ld.acquire.gpu.global.u32 %0, [%1];" : "=r"(v) : "l"(&g_release) : "memory"); }
            while (v < k);
        }
    }
    __syncthreads();
}

// ---- GEMM microkernel: acc lanes = {even-k partial, odd-k partial} ----
// Wt row kp: 32 floats = [i0e i0o f0e f0o g0e g0o o0e o0o i1e ...]
// Hs row kp: 512 floats = [b0e b0o b1e b1o ...]
template<int NKP>
__device__ __forceinline__ void gemm_tile(u64 acc[4][2], const float* __restrict__ Wt,
                                          const float* __restrict__ Hs, int cx, int b2) {
#pragma unroll
    for (int kp = 0; kp < NKP; ++kp) {
        ulonglong2 w01 = *(const ulonglong2*)(Wt + kp * 32 + cx * 8);      // {i},{f}
        ulonglong2 w23 = *(const ulonglong2*)(Wt + kp * 32 + cx * 8 + 4);  // {g},{o}
        ulonglong2 hp  = *(const ulonglong2*)(Hs + kp * 512 + b2 * 4);     // {b0},{b1}
        acc[0][0] = ffma2(hp.x, w01.x, acc[0][0]);
        acc[1][0] = ffma2(hp.x, w01.y, acc[1][0]);
        acc[2][0] = ffma2(hp.x, w23.x, acc[2][0]);
        acc[3][0] = ffma2(hp.x, w23.y, acc[3][0]);
        acc[0][1] = ffma2(hp.y, w01.x, acc[0][1]);
        acc[1][1] = ffma2(hp.y, w01.y, acc[1][1]);
        acc[2][1] = ffma2(hp.y, w23.x, acc[2][1]);
        acc[3][1] = ffma2(hp.y, w23.y, acc[3][1]);
    }
}

__device__ __forceinline__ float sigf(float x) { return 1.0f / (1.0f + __expf(-x)); }

// SMEM floats: Hs(2x8192)=16384 | Wt1 8192 | Wt2a 8192 | Wt2b 8192 | Wtx 256 | bc1 16 | bc2 16
#define SMEM_FLOATS 41248
#define SMEM_BYTES  (SMEM_FLOATS * 4)

__global__ void __launch_bounds__(TPB, 1)
lstm2_persist(const float* __restrict__ x,
              const float* __restrict__ Wih1, const float* __restrict__ Whh1,
              const float* __restrict__ bih1, const float* __restrict__ bhh1,
              const float* __restrict__ Wih2, const float* __restrict__ Whh2,
              const float* __restrict__ bih2, const float* __restrict__ bhh2,
              const float* __restrict__ fc1w, const float* __restrict__ fc1b,
              const float* __restrict__ fcw,  const float* __restrict__ fcb,
              float* __restrict__ out)
{
    extern __shared__ float sm[];
    float* Hsm  = sm;
    float* Wt1  = sm + 16384;
    float* Wt2a = Wt1 + 8192;
    float* Wt2b = Wt2a + 8192;
    float* Wtx  = Wt2b + 8192;
    float* bc1  = Wtx + 256;
    float* bc2  = bc1 + 16;

    const int tid = threadIdx.x;
    const int blk = blockIdx.x;
    const int cx  = tid & 3;         // unit within block
    const int b2  = tid >> 2;        // batch-pair index 0..127
    const int u   = blk * 4 + cx;    // global unit

    // ---- prologue: k-pair-interleaved weight slices ----
    for (int idx = tid; idx < 8192; idx += TPB) {
        int kp = idx >> 5, cc = idx & 31;
        int col = cc >> 1, par = cc & 1;
        int k = 2 * kp + par;
        int r = (col & 3) * 512 + blk * 4 + (col >> 2);   // gate-major rows
        Wt1[idx]  = Whh1[r * 512 + k];
        Wt2a[idx] = Wih2[r * 512 + k];
        Wt2b[idx] = Whh2[r * 512 + k];
    }
    if (tid < 256) {
        int kp = tid >> 5, cc = tid & 31;
        int col = cc >> 1, par = cc & 1;
        int k = 2 * kp + par;
        int r = (col & 3) * 512 + blk * 4 + (col >> 2);
        Wtx[tid] = (k < INDIM) ? Wih1[r * INDIM + k] : 0.0f;
    }
    if (tid < 16) {
        int r = (tid & 3) * 512 + blk * 4 + (tid >> 2);
        bc1[tid] = bih1[r] + bhh1[r];
        bc2[tid] = bih2[r] + bhh2[r];
    }
    // zero h(-1) (parity 1)
    for (int i = blk * TPB + tid; i < HID * BATCH; i += NB * TPB) {
        g_h1[1][i] = 0.0f;
        g_h2[1][i] = 0.0f;
    }
    // x -> pair layout: g_xT[t*4096 + kp*512 + b*2 + par]
    for (int idx = blk * TPB + tid; idx < SEQ * 16 * BATCH; idx += NB * TPB) {
        int t = idx >> 12, rem = idx & 4095;
        int kp = rem >> 9, b = (rem >> 1) & 255, par = rem & 1;
        int k = 2 * kp + par;
        g_xT[idx] = (k < INDIM) ? x[(t * BATCH + b) * INDIM + k] : 0.0f;
    }

    float c1s[2] = {0.f, 0.f};
    float c2s[2] = {0.f, 0.f};
    unsigned barno = 1;
    grid_sync(barno);

    u64 b1g[4], b2g[4];
#pragma unroll
    for (int g = 0; g < 4; ++g) {
        b1g[g] = pk2(bc1[cx * 4 + g], 0.f);
        b2g[g] = pk2(bc2[cx * 4 + g], 0.f);
    }

    for (int t = 0; t < SEQ; ++t) {
        const int p = t & 1;

        // ---- layer 1: K = 512 (h1 prev) + 16 (x, padded) ----
        {
            const float* h1r = g_h1[p ^ 1];
            u64 acc[4][2];
#pragma unroll
            for (int g = 0; g < 4; ++g) { acc[g][0] = b1g[g]; acc[g][1] = b1g[g]; }
            stage(Hsm, h1r, 2048, tid); cp_commit();
            for (int tile = 0; tile < 17; ++tile) {
                float* buf = Hsm + (tile & 1) * 8192;
                cp_wait0();
                __syncthreads();
                if (tile < 16) {
                    float* nbuf = Hsm + ((tile + 1) & 1) * 8192;
                    if (tile < 15) stage(nbuf, h1r + (tile + 1) * 8192, 2048, tid);
                    else           stage(nbuf, &g_xT[t * 4096], 1024, tid);
                    cp_commit();
                    gemm_tile<16>(acc, Wt1 + tile * 512, buf, cx, b2);
                } else {
                    gemm_tile<8>(acc, Wtx, buf, cx, b2);
                }
            }
#pragma unroll
            for (int j = 0; j < 2; ++j) {
                float e, o, gi, gf, gg, go;
                upk2(acc[0][j], e, o); gi = e + o;
                upk2(acc[1][j], e, o); gf = e + o;
                upk2(acc[2][j], e, o); gg = e + o;
                upk2(acc[3][j], e, o); go = e + o;
                float cc = sigf(gf) * c1s[j] + sigf(gi) * tanhf(gg);
                c1s[j] = cc;
                g_h1[p][(u >> 1) * 512 + (2 * b2 + j) * 2 + (u & 1)] = sigf(go) * tanhf(cc);
            }
        }
        grid_sync(++barno);

        // ---- layer 2: K = 512 (h1 cur) + 512 (h2 prev) ----
        {
            const float* h1c = g_h1[p];
            const float* h2r = g_h2[p ^ 1];
            u64 acc[4][2];
#pragma unroll
            for (int g = 0; g < 4; ++g) { acc[g][0] = b2g[g]; acc[g][1] = b2g[g]; }
            stage(Hsm, h1c, 2048, tid); cp_commit();
            for (int tile = 0; tile < 32; ++tile) {
                float* buf = Hsm + (tile & 1) * 8192;
                cp_wait0();
                __syncthreads();
                if (tile + 1 < 32) {
                    float* nbuf = Hsm + ((tile + 1) & 1) * 8192;
                    const float* src = (tile + 1 < 16) ? h1c + (tile + 1) * 8192
                                                       : h2r + (tile + 1 - 16) * 8192;
                    stage(nbuf, src, 2048, tid);
                    cp_commit();
                }
                const float* W = (tile < 16) ? Wt2a + tile * 512 : Wt2b + (tile - 16) * 512;
                gemm_tile<16>(acc, W, buf, cx, b2);
            }
#pragma unroll
            for (int j = 0; j < 2; ++j) {
                float e, o, gi, gf, gg, go;
                upk2(acc[0][j], e, o); gi = e + o;
                upk2(acc[1][j], e, o); gf = e + o;
                upk2(acc[2][j], e, o); gg = e + o;
                upk2(acc[3][j], e, o); go = e + o;
                float cc = sigf(gf) * c2s[j] + sigf(gi) * tanhf(gg);
                c2s[j] = cc;
                g_h2[p][(u >> 1) * 512 + (2 * b2 + j) * 2 + (u & 1)] = sigf(go) * tanhf(cc);
            }
        }
        grid_sync(++barno);
    }

    // ---- MLP head: final h2 is parity 1 ----
    if (blk < 64 && tid < BATCH) {
        float s = fc1b[blk];
        for (int k = 0; k < HID; ++k) {
            float v = __ldcg(&g_h2[1][(k >> 1) * 512 + tid * 2 + (k & 1)]);
            s += fmaxf(v, 0.f) * fc1w[blk * HID + k];
        }
        g_fc1[blk * BATCH + tid] = fmaxf(s, 0.f);
    }
    grid_sync(++barno);
    if (blk == 0 && tid < BATCH) {
        float s = fcb[0];
#pragma unroll
        for (int j = 0; j < 64; ++j)
            s += __ldcg(&g_fc1[j * BATCH + tid]) * fcw[j];
        out[tid] = 2.0f * s;
    }
}

extern "C" void kernel_launch(void* const* d_in, const int* in_sizes, int n_in,
                              void* d_out, int out_size) {
    (void)in_sizes; (void)n_in; (void)out_size;
    cudaFuncSetAttribute(lstm2_persist, cudaFuncAttributeMaxDynamicSharedMemorySize, SMEM_BYTES);
    sync_init_kernel<<<1, 1>>>();
    lstm2_persist<<<NB, TPB, SMEM_BYTES>>>(
        (const float*)d_in[0],
        (const float*)d_in[1], (const float*)d_in[2],
        (const float*)d_in[3], (const float*)d_in[4],
        (const float*)d_in[5], (const float*)d_in[6],
        (const float*)d_in[7], (const float*)d_in[8],
        (const float*)d_in[9], (const float*)d_in[10],
        (const float*)d_in[11], (const float*)d_in[12],
        (float*)d_out);
}